// round 10
// baseline (speedup 1.0000x reference)
#include <cuda_runtime.h>
#include <cuda_bf16.h>
#include <cstdint>

#define N_NODES   100000
#define NODE_PAD  100096            // 782 * 128
#define N_EDGES   1000000
#define N_GRAPHS  1024
#define SCAN_BLK  512
#define N_SCAN_BLKS ((N_NODES + SCAN_BLK - 1) / SCAN_BLK)   // 196
#define EB ((N_EDGES + 255) / 256)  // 3907 edge blocks in prologue
#define NB ((N_NODES + 255) / 256)  // 391 node blocks in prologue

// ---------------- scratch (device globals; zero-initialized at load) --------
// Invariants across calls:
//  - g_deg is zero on entry (BSS; fill_kernel re-zeroes after last use)
//  - g_hist4 is zeroed by prologue role-1 blocks each call, before fill
//  - g_sstate is zeroed by prologue block 0 each call, before the scan
//  - pad rows of g_agg1 are never written, stay zero; pad rows of
//    g_hist4/g_ncls are never written -> h1 pad rows are deterministic
__device__ __align__(16) float g_h1  [NODE_PAD * 64];
__device__ __align__(16) float g_agg1[NODE_PAD * 64];
__device__ __align__(16) float g_h2  [NODE_PAD * 64];
__device__ __align__(16) float g_tabRel  [64 * 64];   // relu_table @ W1_rel
__device__ __align__(16) float g_tabRootB[64 * 64];   // relu_table @ W1_root + b1
__device__ __align__(16) unsigned g_hist4[NODE_PAD * 16];  // 4 packed u8 counts/word
__device__ int g_ncls[NODE_PAD];
__device__ int g_deg[N_NODES];
__device__ int g_off[N_NODES + 1];
__device__ int g_cur[N_NODES];
__device__ unsigned g_eidx[N_EDGES];                  // src node id
__device__ unsigned long long g_sstate[N_SCAN_BLKS];
__device__ int g_gstart[N_GRAPHS + 1];

// ---------------- fused prologue: count+zero | class+bounds | tables --------
__global__ void __launch_bounds__(256) prologue_kernel(
    const int* __restrict__ dst,
    const int* __restrict__ batch,
    const int* __restrict__ x,
    const float* __restrict__ shape_emb,
    const float* __restrict__ color_emb,
    const float* __restrict__ W_node,
    const float* __restrict__ b_node,
    const float* __restrict__ W1_rel,
    const float* __restrict__ W1_root,
    const float* __restrict__ b1)
{
    __shared__ float sWn[16 * 32];
    __shared__ float sS[64], sC[64], sbn[32], sb1[64];
    __shared__ float sT[64 * 32];
    __shared__ float sW1r[32 * 64], sW1o[32 * 64];

    int tid = threadIdx.x;
    int bid = blockIdx.x;
    if (bid < EB) {
        // role 1: degree count + zero hist + reset scan state
        if (bid == 0 && tid < N_SCAN_BLKS) g_sstate[tid] = 0ULL;
        int gtid = bid * 256 + tid;
        for (int j = gtid; j < NODE_PAD * 16; j += EB * 256) g_hist4[j] = 0u;
        if (gtid < N_EDGES) atomicAdd(&g_deg[dst[gtid]], 1);
        return;
    }
    if (bid < EB + NB) {
        // role 2: node class + graph bounds (batch is sorted)
        int n = (bid - EB) * 256 + tid;
        if (n >= N_NODES) return;
        int b1v = batch[n];
        int b0v = (n == 0) ? -1 : batch[n - 1];
        for (int g = b0v + 1; g <= b1v; g++) g_gstart[g] = n;
        if (n == N_NODES - 1)
            for (int g = b1v + 1; g <= N_GRAPHS; g++) g_gstart[g] = N_NODES;
        g_ncls[n] = x[2 * n] * 8 + x[2 * n + 1];
        return;
    }
    // role 3: build layer-1 class tables (single block)
    for (int i = tid; i < 512; i += 256) sWn[i] = W_node[i];
    if (tid < 64) { sS[tid] = shape_emb[tid]; sC[tid] = color_emb[tid]; sb1[tid] = b1[tid]; }
    if (tid < 32) sbn[tid] = b_node[tid];
    for (int i = tid; i < 2048; i += 256) { sW1r[i] = W1_rel[i]; sW1o[i] = W1_root[i]; }
    __syncthreads();
    // relu table rows: 64 classes x 32 cols (4 threads per class, 8 cols each)
    {
        int c = tid >> 2, q = tid & 3;
        int sh = c >> 3, co = c & 7;
        for (int j = q * 8; j < q * 8 + 8; j++) {
            float a = sbn[j];
#pragma unroll
            for (int k = 0; k < 8; k++)
                a += sS[sh * 8 + k] * sWn[k * 32 + j]
                   + sC[co * 8 + k] * sWn[(8 + k) * 32 + j];
            sT[c * 32 + j] = fmaxf(a, 0.f);
        }
    }
    __syncthreads();
    for (int i = tid; i < 4096; i += 256) {
        int c = i >> 6, j = i & 63;
        float ar = 0.f, ao = sb1[j];
#pragma unroll
        for (int k = 0; k < 32; k++) {
            float t = sT[c * 32 + k];
            ar += t * sW1r[k * 64 + j];
            ao += t * sW1o[k * 64 + j];
        }
        g_tabRel[i]   = ar;
        g_tabRootB[i] = ao;
    }
}

// ---------------- single-pass scan (decoupled lookback) ---------------------
__global__ void __launch_bounds__(SCAN_BLK) scan_kernel() {
    __shared__ int s[SCAN_BLK];
    __shared__ int sprefix;
    int bid = blockIdx.x, tid = threadIdx.x;
    int n = bid * SCAN_BLK + tid;
    int d = (n < N_NODES) ? g_deg[n] : 0;
    s[tid] = d;
    __syncthreads();
    for (int off = 1; off < SCAN_BLK; off <<= 1) {
        int v = (tid >= off) ? s[tid - off] : 0;
        __syncthreads();
        s[tid] += v;
        __syncthreads();
    }
    int agg = s[SCAN_BLK - 1];

    if (tid == 0) {
        if (bid == 0) {
            atomicExch(&g_sstate[0], ((unsigned long long)agg << 2) | 2ULL);
            sprefix = 0;
        } else {
            atomicExch(&g_sstate[bid], ((unsigned long long)agg << 2) | 1ULL);
            long long ex = 0;
            int p = bid - 1;
            for (;;) {
                unsigned long long v;
                do { v = atomicOr(&g_sstate[p], 0ULL); } while ((v & 3ULL) == 0ULL);
                ex += (long long)(v >> 2);
                if ((v & 3ULL) == 2ULL) break;
                p--;
            }
            atomicExch(&g_sstate[bid],
                       ((unsigned long long)(ex + agg) << 2) | 2ULL);
            sprefix = (int)ex;
        }
    }
    __syncthreads();
    int pre = sprefix;
    if (n < N_NODES) {
        int o = pre + s[tid] - d;   // exclusive
        g_off[n] = o;
        g_cur[n] = o;
    }
    if (bid == N_SCAN_BLKS - 1 && tid == SCAN_BLK - 1)
        g_off[N_NODES] = pre + agg;
}

// fill CSR + class histogram; restore g_deg==0 invariant for the next call
__global__ void fill_kernel(const int* __restrict__ src, const int* __restrict__ dst) {
    int e = blockIdx.x * blockDim.x + threadIdx.x;
    if (e < N_NODES) g_deg[e] = 0;
    if (e >= N_EDGES) return;
    int d = dst[e];
    int s = src[e];
    int c = g_ncls[s];
    int pos = atomicAdd(&g_cur[d], 1);
    g_eidx[pos] = (unsigned)s;
    atomicAdd(&g_hist4[d * 16 + (c >> 2)], 1u << ((c & 3) * 8));
}

// ---------------- shared MMA helpers ----------------------------------------
__device__ __forceinline__ uint32_t f2tf32(float f) {
    uint32_t u;
    asm("cvt.rna.tf32.f32 %0, %1;" : "=r"(u) : "f"(f));
    return u;
}

__device__ __forceinline__ void mma_tf32(float c[4],
                                         uint32_t a0, uint32_t a1, uint32_t a2, uint32_t a3,
                                         uint32_t b0, uint32_t b1) {
    asm volatile(
        "mma.sync.aligned.m16n8k8.row.col.f32.tf32.tf32.f32 "
        "{%0,%1,%2,%3}, {%4,%5,%6,%7}, {%8,%9}, {%0,%1,%2,%3};"
        : "+f"(c[0]), "+f"(c[1]), "+f"(c[2]), "+f"(c[3])
        : "r"(a0), "r"(a1), "r"(a2), "r"(a3), "r"(b0), "r"(b1));
}

// ---------------- layer 1 GEMM: h1 = relu(hist @ tabRel + tabRootB[cls]) ----
// M=NODE_PAD, K=64, N=64; A = per-node class counts (exact small ints).
__global__ void __launch_bounds__(256) conv1_kernel() {
    constexpr int STEPS = 8;
    constexpr int LDB = 72;
    constexpr int SAS = 68;

    extern __shared__ char smem[];
    uint32_t* sW    = (uint32_t*)smem;                 // 64 * 72
    float*    sRoot = (float*)(smem + 64 * LDB * 4);   // 64 * 64
    float*    sA    = sRoot + 64 * 64;                 // 128 * 68

    int tid = threadIdx.x;
    int base = blockIdx.x * 128;

    for (int i = tid; i < 64 * 64; i += 256) {
        int k = i >> 6, n = i & 63;
        sW[k * LDB + n] = f2tf32(g_tabRel[i]);
        sRoot[i] = g_tabRootB[i];
    }
    // stage histogram -> fp32 counts
    for (int i = tid; i < 128 * 16; i += 256) {
        int row = i >> 4, w = i & 15;
        unsigned v = g_hist4[(size_t)(base + row) * 16 + w];
        float4 f;
        f.x = (float)(v & 0xffu);
        f.y = (float)((v >> 8) & 0xffu);
        f.z = (float)((v >> 16) & 0xffu);
        f.w = (float)(v >> 24);
        *(float4*)&sA[row * SAS + w * 4] = f;
    }
    __syncthreads();

    int lane = tid & 31, wid = tid >> 5;
    int wm = wid >> 1, wn = wid & 1;
    int r4 = lane >> 2, c4 = lane & 3;
    int nl0 = wm * 32 + r4;

    float acc[2][4][4];
#pragma unroll
    for (int t = 0; t < 2; t++)
#pragma unroll
        for (int u = 0; u < 4; u++)
#pragma unroll
            for (int v = 0; v < 4; v++) acc[t][u][v] = 0.f;

#pragma unroll
    for (int s = 0; s < STEPS; s++) {
        int koff = s * 8 + c4;
        uint32_t a[2][4];
#pragma unroll
        for (int t = 0; t < 2; t++) {
            const float* p0 = sA + (nl0 + t * 16) * SAS + koff;
            const float* p8 = sA + (nl0 + t * 16 + 8) * SAS + koff;
            a[t][0] = f2tf32(p0[0]);
            a[t][1] = f2tf32(p8[0]);
            a[t][2] = f2tf32(p0[4]);
            a[t][3] = f2tf32(p8[4]);
        }
        int krow = s * 8 + c4;
        uint32_t bf[4][2];
#pragma unroll
        for (int u = 0; u < 4; u++) {
            int col = wn * 32 + u * 8 + r4;
            bf[u][0] = sW[krow * LDB + col];
            bf[u][1] = sW[(krow + 4) * LDB + col];
        }
#pragma unroll
        for (int t = 0; t < 2; t++)
#pragma unroll
            for (int u = 0; u < 4; u++)
                mma_tf32(acc[t][u], a[t][0], a[t][1], a[t][2], a[t][3],
                         bf[u][0], bf[u][1]);
    }

#pragma unroll
    for (int t = 0; t < 2; t++) {
        int row = base + wm * 32 + t * 16 + r4;
        int cls0 = g_ncls[row];
        int cls8 = g_ncls[row + 8];
#pragma unroll
        for (int u = 0; u < 4; u++) {
            int col = wn * 32 + u * 8 + c4 * 2;
            float2 r0 = *(const float2*)&sRoot[cls0 * 64 + col];
            float2 r8 = *(const float2*)&sRoot[cls8 * 64 + col];
            float2 lo = make_float2(fmaxf(acc[t][u][0] + r0.x, 0.f),
                                    fmaxf(acc[t][u][1] + r0.y, 0.f));
            float2 hi = make_float2(fmaxf(acc[t][u][2] + r8.x, 0.f),
                                    fmaxf(acc[t][u][3] + r8.y, 0.f));
            *(float2*)&g_h1[(size_t)row * 64 + col]       = lo;
            *(float2*)&g_h1[(size_t)(row + 8) * 64 + col] = hi;
        }
    }
}

// ---------------- gather64: agg1[v] = sum h1[src] (prefetch + shfl) ---------
__global__ void __launch_bounds__(256) gather64_kernel() {
    int w = (blockIdx.x * 256 + threadIdx.x) >> 5;
    int lane = threadIdx.x & 31;
    if (w >= N_NODES) return;
    int s0 = g_off[w], s1 = g_off[w + 1];
    float2 acc = make_float2(0.f, 0.f);
    for (int i = s0; i < s1; i += 32) {
        unsigned pv = (i + lane < s1) ? g_eidx[i + lane] : 0u;
        int cnt = s1 - i;
        if (cnt > 32) cnt = 32;
        for (int j = 0; j < cnt; j++) {
            unsigned idx = __shfl_sync(0xffffffff, pv, j);
            float2 v = *(const float2*)(g_h1 + idx * 64u + 2u * lane);
            acc.x += v.x;
            acc.y += v.y;
        }
    }
    *(float2*)(g_agg1 + (unsigned)w * 64u + 2u * lane) = acc;
}

// ---------------- tf32 tensor-core conv (layer 2), smem-staged A ------------
__global__ void __launch_bounds__(256) conv2_kernel(
    const float* __restrict__ Wrel,
    const float* __restrict__ Wroot,
    const float* __restrict__ b)
{
    constexpr int KIN = 64;
    constexpr int K2 = 128;
    constexpr int STEPS = 16;
    constexpr int LDB = 72;
    constexpr int SAS = KIN + 4;
    constexpr int QR  = KIN / 4;

    extern __shared__ char smem[];
    uint32_t* sW = (uint32_t*)smem;                        // K2 * LDB
    float*    sb = (float*)(smem + (size_t)K2 * LDB * 4);  // 64
    float*    sA = sb + 64;                                // 128 * SAS
    float*    sH = sA + 128 * SAS;                         // 128 * SAS

    int tid = threadIdx.x;
    int base = blockIdx.x * 128;

    for (int i = tid; i < K2 * 64; i += 256) {
        int k = i >> 6, n = i & 63;
        float v = (k < KIN) ? Wrel[k * 64 + n] : Wroot[(k - KIN) * 64 + n];
        sW[k * LDB + n] = f2tf32(v);
    }
    if (tid < 64) sb[tid] = b[tid];

    for (int i = tid; i < 128 * QR; i += 256) {
        int row = i / QR, q = i % QR;
        float4 a4 = *(const float4*)(g_agg1 + (size_t)(base + row) * KIN + q * 4);
        float4 h4 = *(const float4*)(g_h1   + (size_t)(base + row) * KIN + q * 4);
        *(float4*)&sA[row * SAS + q * 4] = a4;
        *(float4*)&sH[row * SAS + q * 4] = h4;
    }
    __syncthreads();

    int lane = tid & 31, wid = tid >> 5;
    int wm = wid >> 1, wn = wid & 1;
    int r4 = lane >> 2, c4 = lane & 3;
    int nl0 = wm * 32 + r4;

    float acc[2][4][4];
#pragma unroll
    for (int t = 0; t < 2; t++)
#pragma unroll
        for (int u = 0; u < 4; u++) {
            int col = wn * 32 + u * 8 + c4 * 2;
            acc[t][u][0] = sb[col];
            acc[t][u][1] = sb[col + 1];
            acc[t][u][2] = sb[col];
            acc[t][u][3] = sb[col + 1];
        }

#pragma unroll
    for (int s = 0; s < STEPS; s++) {
        const float* S = (s * 8 < KIN) ? sA : sH;
        int koff = s * 8 - ((s * 8 < KIN) ? 0 : KIN) + c4;

        uint32_t a[2][4];
#pragma unroll
        for (int t = 0; t < 2; t++) {
            const float* p0 = S + (nl0 + t * 16) * SAS + koff;
            const float* p8 = S + (nl0 + t * 16 + 8) * SAS + koff;
            a[t][0] = f2tf32(p0[0]);
            a[t][1] = f2tf32(p8[0]);
            a[t][2] = f2tf32(p0[4]);
            a[t][3] = f2tf32(p8[4]);
        }

        int krow = s * 8 + c4;
        uint32_t bf[4][2];
#pragma unroll
        for (int u = 0; u < 4; u++) {
            int col = wn * 32 + u * 8 + r4;
            bf[u][0] = sW[krow * LDB + col];
            bf[u][1] = sW[(krow + 4) * LDB + col];
        }

#pragma unroll
        for (int t = 0; t < 2; t++)
#pragma unroll
            for (int u = 0; u < 4; u++)
                mma_tf32(acc[t][u], a[t][0], a[t][1], a[t][2], a[t][3],
                         bf[u][0], bf[u][1]);
    }

#pragma unroll
    for (int t = 0; t < 2; t++) {
        int row = base + wm * 32 + t * 16 + r4;
#pragma unroll
        for (int u = 0; u < 4; u++) {
            int col = wn * 32 + u * 8 + c4 * 2;
            float2 lo = make_float2(fmaxf(acc[t][u][0], 0.f), fmaxf(acc[t][u][1], 0.f));
            float2 hi = make_float2(fmaxf(acc[t][u][2], 0.f), fmaxf(acc[t][u][3], 0.f));
            *(float2*)&g_h2[(size_t)row * 64 + col]       = lo;
            *(float2*)&g_h2[(size_t)(row + 8) * 64 + col] = hi;
        }
    }
}

// ---------------- fused mean-pool + classifier ------------------------------
__global__ void __launch_bounds__(64) poolcls_kernel(
    const float* __restrict__ W_cls,
    const float* __restrict__ b_cls,
    float* __restrict__ out)
{
    int g = blockIdx.x;
    int tid = threadIdx.x;
    int s = g_gstart[g], e = g_gstart[g + 1];
    float acc = 0.f;
    for (int n = s; n < e; n++) acc += g_h2[(size_t)n * 64 + tid];
    float cnt = fmaxf((float)(e - s), 1.0f);
    __shared__ float sp[64];
    sp[tid] = acc / cnt;
    __syncthreads();
    if (tid < 10) {
        float dot = b_cls[tid];
#pragma unroll 8
        for (int k = 0; k < 64; k++) dot += sp[k] * W_cls[k * 10 + tid];
        out[(size_t)g * 10 + tid] = dot;
    }
}

// ---------------- launch ------------------------------------------------------
extern "C" void kernel_launch(void* const* d_in, const int* in_sizes, int n_in,
                              void* d_out, int out_size)
{
    const int*   x         = (const int*)  d_in[0];
    const int*   edge_index= (const int*)  d_in[1];
    const int*   batch     = (const int*)  d_in[2];
    const float* shape_emb = (const float*)d_in[3];
    const float* color_emb = (const float*)d_in[4];
    const float* W_node    = (const float*)d_in[5];
    const float* b_node    = (const float*)d_in[6];
    const float* W1_rel    = (const float*)d_in[7];
    const float* W1_root   = (const float*)d_in[8];
    const float* b1        = (const float*)d_in[9];
    const float* W2_rel    = (const float*)d_in[10];
    const float* W2_root   = (const float*)d_in[11];
    const float* b2        = (const float*)d_in[12];
    const float* W_cls     = (const float*)d_in[13];
    const float* b_cls     = (const float*)d_in[14];
    float* out = (float*)d_out;

    const int* src = edge_index;            // edge_index[0, :]
    const int* dst = edge_index + N_EDGES;  // edge_index[1, :]

    const int smem1  = 64 * 72 * 4 + 64 * 64 * 4 + 128 * 68 * 4;   // ~70 KB
    const int smem64 = 128 * 72 * 4 + 64 * 4 + 2 * 128 * 68 * 4;   // ~105 KB
    cudaFuncSetAttribute(conv1_kernel,
                         cudaFuncAttributeMaxDynamicSharedMemorySize, smem1);
    cudaFuncSetAttribute(conv2_kernel,
                         cudaFuncAttributeMaxDynamicSharedMemorySize, smem64);

    prologue_kernel<<<EB + NB + 1, 256>>>(dst, batch, x, shape_emb, color_emb,
                                          W_node, b_node, W1_rel, W1_root, b1);
    scan_kernel<<<N_SCAN_BLKS, SCAN_BLK>>>();
    fill_kernel<<<(N_EDGES + 255) / 256, 256>>>(src, dst);

    conv1_kernel<<<NODE_PAD / 128, 256, smem1>>>();
    gather64_kernel<<<(N_NODES + 7) / 8, 256>>>();
    conv2_kernel<<<NODE_PAD / 128, 256, smem64>>>(W2_rel, W2_root, b2);

    poolcls_kernel<<<N_GRAPHS, 64>>>(W_cls, b_cls, out);
}

// round 12
// speedup vs baseline: 1.0576x; 1.0576x over previous
#include <cuda_runtime.h>
#include <cuda_bf16.h>
#include <cstdint>

#define N_NODES   100000
#define NODE_PAD  100096            // 782 * 128
#define N_TILES   (NODE_PAD / 128)  // 782
#define N_EDGES   1000000
#define N_GRAPHS  1024
#define SCAN_BLK  512
#define N_SCAN_BLKS ((N_NODES + SCAN_BLK - 1) / SCAN_BLK)   // 196
#define EB ((N_EDGES + 255) / 256)  // 3907 edge blocks in prologue
#define NB ((N_NODES + 255) / 256)  // 391 node blocks in prologue

// ---------------- scratch (device globals; zero-initialized at load) --------
// Invariants across calls:
//  - g_deg is zero on entry (BSS; fill_kernel re-zeroes after last use)
//  - g_hist4 is zeroed by prologue role-1 blocks each call, before fill
//  - g_sstate is zeroed by prologue block 0 each call, before the scan
//  - pad rows of g_agg1 are never written, stay zero; pad rows of
//    g_hist4/g_ncls are never written -> h1 pad rows are deterministic
__device__ __align__(16) float g_h1  [NODE_PAD * 64];
__device__ __align__(16) float g_agg1[NODE_PAD * 64];
__device__ __align__(16) float g_h2  [NODE_PAD * 64];
__device__ __align__(16) float g_tabRel  [64 * 64];   // relu_table @ W1_rel
__device__ __align__(16) float g_tabRootB[64 * 64];   // relu_table @ W1_root + b1
__device__ __align__(16) unsigned g_hist4[NODE_PAD * 16];  // 4 packed u8 counts/word
__device__ int g_ncls[NODE_PAD];
__device__ int g_deg[N_NODES];
__device__ int g_off[N_NODES + 1];
__device__ int g_cur[N_NODES];
__device__ unsigned g_eidx[N_EDGES];                  // src node id
__device__ unsigned long long g_sstate[N_SCAN_BLKS];
__device__ int g_gstart[N_GRAPHS + 1];

// ---------------- fused prologue: count+zero | class+bounds | tables --------
__global__ void __launch_bounds__(256) prologue_kernel(
    const int* __restrict__ dst,
    const int* __restrict__ batch,
    const int* __restrict__ x,
    const float* __restrict__ shape_emb,
    const float* __restrict__ color_emb,
    const float* __restrict__ W_node,
    const float* __restrict__ b_node,
    const float* __restrict__ W1_rel,
    const float* __restrict__ W1_root,
    const float* __restrict__ b1)
{
    __shared__ float sWn[16 * 32];
    __shared__ float sS[64], sC[64], sbn[32], sb1[64];
    __shared__ float sT[64 * 32];
    __shared__ float sW1r[32 * 64], sW1o[32 * 64];

    int tid = threadIdx.x;
    int bid = blockIdx.x;
    if (bid < EB) {
        // role 1: degree count + zero hist + reset scan state
        if (bid == 0 && tid < N_SCAN_BLKS) g_sstate[tid] = 0ULL;
        int gtid = bid * 256 + tid;
        for (int j = gtid; j < NODE_PAD * 16; j += EB * 256) g_hist4[j] = 0u;
        if (gtid < N_EDGES) atomicAdd(&g_deg[dst[gtid]], 1);
        return;
    }
    if (bid < EB + NB) {
        // role 2: node class + graph bounds (batch is sorted)
        int n = (bid - EB) * 256 + tid;
        if (n >= N_NODES) return;
        int b1v = batch[n];
        int b0v = (n == 0) ? -1 : batch[n - 1];
        for (int g = b0v + 1; g <= b1v; g++) g_gstart[g] = n;
        if (n == N_NODES - 1)
            for (int g = b1v + 1; g <= N_GRAPHS; g++) g_gstart[g] = N_NODES;
        g_ncls[n] = x[2 * n] * 8 + x[2 * n + 1];
        return;
    }
    // role 3: build layer-1 class tables (single block)
    for (int i = tid; i < 512; i += 256) sWn[i] = W_node[i];
    if (tid < 64) { sS[tid] = shape_emb[tid]; sC[tid] = color_emb[tid]; sb1[tid] = b1[tid]; }
    if (tid < 32) sbn[tid] = b_node[tid];
    for (int i = tid; i < 2048; i += 256) { sW1r[i] = W1_rel[i]; sW1o[i] = W1_root[i]; }
    __syncthreads();
    // relu table rows: 64 classes x 32 cols (4 threads per class, 8 cols each)
    {
        int c = tid >> 2, q = tid & 3;
        int sh = c >> 3, co = c & 7;
        for (int j = q * 8; j < q * 8 + 8; j++) {
            float a = sbn[j];
#pragma unroll
            for (int k = 0; k < 8; k++)
                a += sS[sh * 8 + k] * sWn[k * 32 + j]
                   + sC[co * 8 + k] * sWn[(8 + k) * 32 + j];
            sT[c * 32 + j] = fmaxf(a, 0.f);
        }
    }
    __syncthreads();
    for (int i = tid; i < 4096; i += 256) {
        int c = i >> 6, j = i & 63;
        float ar = 0.f, ao = sb1[j];
#pragma unroll
        for (int k = 0; k < 32; k++) {
            float t = sT[c * 32 + k];
            ar += t * sW1r[k * 64 + j];
            ao += t * sW1o[k * 64 + j];
        }
        g_tabRel[i]   = ar;
        g_tabRootB[i] = ao;
    }
}

// ---------------- single-pass scan (decoupled lookback) ---------------------
__global__ void __launch_bounds__(SCAN_BLK) scan_kernel() {
    __shared__ int s[SCAN_BLK];
    __shared__ int sprefix;
    int bid = blockIdx.x, tid = threadIdx.x;
    int n = bid * SCAN_BLK + tid;
    int d = (n < N_NODES) ? g_deg[n] : 0;
    s[tid] = d;
    __syncthreads();
    for (int off = 1; off < SCAN_BLK; off <<= 1) {
        int v = (tid >= off) ? s[tid - off] : 0;
        __syncthreads();
        s[tid] += v;
        __syncthreads();
    }
    int agg = s[SCAN_BLK - 1];

    if (tid == 0) {
        if (bid == 0) {
            atomicExch(&g_sstate[0], ((unsigned long long)agg << 2) | 2ULL);
            sprefix = 0;
        } else {
            atomicExch(&g_sstate[bid], ((unsigned long long)agg << 2) | 1ULL);
            long long ex = 0;
            int p = bid - 1;
            for (;;) {
                unsigned long long v;
                do { v = atomicOr(&g_sstate[p], 0ULL); } while ((v & 3ULL) == 0ULL);
                ex += (long long)(v >> 2);
                if ((v & 3ULL) == 2ULL) break;
                p--;
            }
            atomicExch(&g_sstate[bid],
                       ((unsigned long long)(ex + agg) << 2) | 2ULL);
            sprefix = (int)ex;
        }
    }
    __syncthreads();
    int pre = sprefix;
    if (n < N_NODES) {
        int o = pre + s[tid] - d;   // exclusive
        g_off[n] = o;
        g_cur[n] = o;
    }
    if (bid == N_SCAN_BLKS - 1 && tid == SCAN_BLK - 1)
        g_off[N_NODES] = pre + agg;
}

// fill CSR + class histogram; restore g_deg==0 invariant for the next call
__global__ void fill_kernel(const int* __restrict__ src, const int* __restrict__ dst) {
    int e = blockIdx.x * blockDim.x + threadIdx.x;
    if (e < N_NODES) g_deg[e] = 0;
    if (e >= N_EDGES) return;
    int d = dst[e];
    int s = src[e];
    int c = g_ncls[s];
    int pos = atomicAdd(&g_cur[d], 1);
    g_eidx[pos] = (unsigned)s;
    atomicAdd(&g_hist4[d * 16 + (c >> 2)], 1u << ((c & 3) * 8));
}

// ---------------- shared MMA helpers ----------------------------------------
__device__ __forceinline__ uint32_t f2tf32(float f) {
    uint32_t u;
    asm("cvt.rna.tf32.f32 %0, %1;" : "=r"(u) : "f"(f));
    return u;
}

__device__ __forceinline__ void mma_tf32(float c[4],
                                         uint32_t a0, uint32_t a1, uint32_t a2, uint32_t a3,
                                         uint32_t b0, uint32_t b1) {
    asm volatile(
        "mma.sync.aligned.m16n8k8.row.col.f32.tf32.tf32.f32 "
        "{%0,%1,%2,%3}, {%4,%5,%6,%7}, {%8,%9}, {%0,%1,%2,%3};"
        : "+f"(c[0]), "+f"(c[1]), "+f"(c[2]), "+f"(c[3])
        : "r"(a0), "r"(a1), "r"(a2), "r"(a3), "r"(b0), "r"(b1));
}

// ---------------- layer 1 GEMM (persistent): h1 = relu(hist@tabRel + root) --
__global__ void __launch_bounds__(256) conv1_kernel() {
    constexpr int STEPS = 8;
    constexpr int LDB = 72;
    constexpr int SAS = 68;

    extern __shared__ char smem[];
    uint32_t* sW    = (uint32_t*)smem;                 // 64 * 72
    float*    sRoot = (float*)(smem + 64 * LDB * 4);   // 64 * 64
    float*    sA    = sRoot + 64 * 64;                 // 128 * 68

    int tid = threadIdx.x;

    // one-time table load
    for (int i = tid; i < 64 * 64; i += 256) {
        int k = i >> 6, n = i & 63;
        sW[k * LDB + n] = f2tf32(g_tabRel[i]);
        sRoot[i] = g_tabRootB[i];
    }

    int lane = tid & 31, wid = tid >> 5;
    int wm = wid >> 1, wn = wid & 1;
    int r4 = lane >> 2, c4 = lane & 3;
    int nl0 = wm * 32 + r4;
    __syncthreads();

    for (int tile = blockIdx.x; tile < N_TILES; tile += gridDim.x) {
        int base = tile * 128;
        // stage histogram -> fp32 counts
#pragma unroll 2
        for (int i = tid; i < 128 * 16; i += 256) {
            int row = i >> 4, w = i & 15;
            unsigned v = g_hist4[(size_t)(base + row) * 16 + w];
            float4 f;
            f.x = (float)(v & 0xffu);
            f.y = (float)((v >> 8) & 0xffu);
            f.z = (float)((v >> 16) & 0xffu);
            f.w = (float)(v >> 24);
            *(float4*)&sA[row * SAS + w * 4] = f;
        }
        __syncthreads();

        float acc[2][4][4];
#pragma unroll
        for (int t = 0; t < 2; t++)
#pragma unroll
            for (int u = 0; u < 4; u++)
#pragma unroll
                for (int v = 0; v < 4; v++) acc[t][u][v] = 0.f;

#pragma unroll
        for (int s = 0; s < STEPS; s++) {
            int koff = s * 8 + c4;
            uint32_t a[2][4];
#pragma unroll
            for (int t = 0; t < 2; t++) {
                const float* p0 = sA + (nl0 + t * 16) * SAS + koff;
                const float* p8 = sA + (nl0 + t * 16 + 8) * SAS + koff;
                a[t][0] = f2tf32(p0[0]);
                a[t][1] = f2tf32(p8[0]);
                a[t][2] = f2tf32(p0[4]);
                a[t][3] = f2tf32(p8[4]);
            }
            int krow = s * 8 + c4;
            uint32_t bf[4][2];
#pragma unroll
            for (int u = 0; u < 4; u++) {
                int col = wn * 32 + u * 8 + r4;
                bf[u][0] = sW[krow * LDB + col];
                bf[u][1] = sW[(krow + 4) * LDB + col];
            }
#pragma unroll
            for (int t = 0; t < 2; t++)
#pragma unroll
                for (int u = 0; u < 4; u++)
                    mma_tf32(acc[t][u], a[t][0], a[t][1], a[t][2], a[t][3],
                             bf[u][0], bf[u][1]);
        }

#pragma unroll
        for (int t = 0; t < 2; t++) {
            int row = base + wm * 32 + t * 16 + r4;
            int cls0 = g_ncls[row];
            int cls8 = g_ncls[row + 8];
#pragma unroll
            for (int u = 0; u < 4; u++) {
                int col = wn * 32 + u * 8 + c4 * 2;
                float2 r0 = *(const float2*)&sRoot[cls0 * 64 + col];
                float2 r8 = *(const float2*)&sRoot[cls8 * 64 + col];
                float2 lo = make_float2(fmaxf(acc[t][u][0] + r0.x, 0.f),
                                        fmaxf(acc[t][u][1] + r0.y, 0.f));
                float2 hi = make_float2(fmaxf(acc[t][u][2] + r8.x, 0.f),
                                        fmaxf(acc[t][u][3] + r8.y, 0.f));
                *(float2*)&g_h1[(size_t)row * 64 + col]       = lo;
                *(float2*)&g_h1[(size_t)(row + 8) * 64 + col] = hi;
            }
        }
        __syncthreads();   // protect sA from next-tile staging
    }
}

// ---------------- gather64: agg1[v] = sum h1[src] (prefetch + shfl) ---------
__global__ void __launch_bounds__(256) gather64_kernel() {
    int w = (blockIdx.x * 256 + threadIdx.x) >> 5;
    int lane = threadIdx.x & 31;
    if (w >= N_NODES) return;
    int s0 = g_off[w], s1 = g_off[w + 1];
    float2 acc = make_float2(0.f, 0.f);
    for (int i = s0; i < s1; i += 32) {
        unsigned pv = (i + lane < s1) ? g_eidx[i + lane] : 0u;
        int cnt = s1 - i;
        if (cnt > 32) cnt = 32;
        for (int j = 0; j < cnt; j++) {
            unsigned idx = __shfl_sync(0xffffffff, pv, j);
            float2 v = *(const float2*)(g_h1 + idx * 64u + 2u * lane);
            acc.x += v.x;
            acc.y += v.y;
        }
    }
    *(float2*)(g_agg1 + (unsigned)w * 64u + 2u * lane) = acc;
}

// ---------------- layer 2 conv (persistent), smem-staged A ------------------
__global__ void __launch_bounds__(256) conv2_kernel(
    const float* __restrict__ Wrel,
    const float* __restrict__ Wroot,
    const float* __restrict__ b)
{
    constexpr int KIN = 64;
    constexpr int K2 = 128;
    constexpr int STEPS = 16;
    constexpr int LDB = 72;
    constexpr int SAS = KIN + 4;
    constexpr int QR  = KIN / 4;

    extern __shared__ char smem[];
    uint32_t* sW = (uint32_t*)smem;                        // K2 * LDB
    float*    sb = (float*)(smem + (size_t)K2 * LDB * 4);  // 64
    float*    sA = sb + 64;                                // 128 * SAS
    float*    sH = sA + 128 * SAS;                         // 128 * SAS

    int tid = threadIdx.x;

    // one-time weight load
    for (int i = tid; i < K2 * 64; i += 256) {
        int k = i >> 6, n = i & 63;
        float v = (k < KIN) ? Wrel[k * 64 + n] : Wroot[(k - KIN) * 64 + n];
        sW[k * LDB + n] = f2tf32(v);
    }
    if (tid < 64) sb[tid] = b[tid];

    int lane = tid & 31, wid = tid >> 5;
    int wm = wid >> 1, wn = wid & 1;
    int r4 = lane >> 2, c4 = lane & 3;
    int nl0 = wm * 32 + r4;
    __syncthreads();

    for (int tile = blockIdx.x; tile < N_TILES; tile += gridDim.x) {
        int base = tile * 128;
        for (int i = tid; i < 128 * QR; i += 256) {
            int row = i / QR, q = i % QR;
            float4 a4 = *(const float4*)(g_agg1 + (size_t)(base + row) * KIN + q * 4);
            float4 h4 = *(const float4*)(g_h1   + (size_t)(base + row) * KIN + q * 4);
            *(float4*)&sA[row * SAS + q * 4] = a4;
            *(float4*)&sH[row * SAS + q * 4] = h4;
        }
        __syncthreads();

        float acc[2][4][4];
#pragma unroll
        for (int t = 0; t < 2; t++)
#pragma unroll
            for (int u = 0; u < 4; u++) {
                int col = wn * 32 + u * 8 + c4 * 2;
                acc[t][u][0] = sb[col];
                acc[t][u][1] = sb[col + 1];
                acc[t][u][2] = sb[col];
                acc[t][u][3] = sb[col + 1];
            }

#pragma unroll
        for (int s = 0; s < STEPS; s++) {
            const float* S = (s * 8 < KIN) ? sA : sH;
            int koff = s * 8 - ((s * 8 < KIN) ? 0 : KIN) + c4;

            uint32_t a[2][4];
#pragma unroll
            for (int t = 0; t < 2; t++) {
                const float* p0 = S + (nl0 + t * 16) * SAS + koff;
                const float* p8 = S + (nl0 + t * 16 + 8) * SAS + koff;
                a[t][0] = f2tf32(p0[0]);
                a[t][1] = f2tf32(p8[0]);
                a[t][2] = f2tf32(p0[4]);
                a[t][3] = f2tf32(p8[4]);
            }

            int krow = s * 8 + c4;
            uint32_t bf[4][2];
#pragma unroll
            for (int u = 0; u < 4; u++) {
                int col = wn * 32 + u * 8 + r4;
                bf[u][0] = sW[krow * LDB + col];
                bf[u][1] = sW[(krow + 4) * LDB + col];
            }

#pragma unroll
            for (int t = 0; t < 2; t++)
#pragma unroll
                for (int u = 0; u < 4; u++)
                    mma_tf32(acc[t][u], a[t][0], a[t][1], a[t][2], a[t][3],
                             bf[u][0], bf[u][1]);
        }

#pragma unroll
        for (int t = 0; t < 2; t++) {
            int row = base + wm * 32 + t * 16 + r4;
#pragma unroll
            for (int u = 0; u < 4; u++) {
                int col = wn * 32 + u * 8 + c4 * 2;
                float2 lo = make_float2(fmaxf(acc[t][u][0], 0.f), fmaxf(acc[t][u][1], 0.f));
                float2 hi = make_float2(fmaxf(acc[t][u][2], 0.f), fmaxf(acc[t][u][3], 0.f));
                *(float2*)&g_h2[(size_t)row * 64 + col]       = lo;
                *(float2*)&g_h2[(size_t)(row + 8) * 64 + col] = hi;
            }
        }
        __syncthreads();   // protect sA/sH from next-tile staging
    }
}

// ---------------- fused mean-pool + classifier ------------------------------
__global__ void __launch_bounds__(64) poolcls_kernel(
    const float* __restrict__ W_cls,
    const float* __restrict__ b_cls,
    float* __restrict__ out)
{
    int g = blockIdx.x;
    int tid = threadIdx.x;
    int s = g_gstart[g], e = g_gstart[g + 1];
    float acc = 0.f;
    for (int n = s; n < e; n++) acc += g_h2[(size_t)n * 64 + tid];
    float cnt = fmaxf((float)(e - s), 1.0f);
    __shared__ float sp[64];
    sp[tid] = acc / cnt;
    __syncthreads();
    if (tid < 10) {
        float dot = b_cls[tid];
#pragma unroll 8
        for (int k = 0; k < 64; k++) dot += sp[k] * W_cls[k * 10 + tid];
        out[(size_t)g * 10 + tid] = dot;
    }
}

// ---------------- launch ------------------------------------------------------
extern "C" void kernel_launch(void* const* d_in, const int* in_sizes, int n_in,
                              void* d_out, int out_size)
{
    const int*   x         = (const int*)  d_in[0];
    const int*   edge_index= (const int*)  d_in[1];
    const int*   batch     = (const int*)  d_in[2];
    const float* shape_emb = (const float*)d_in[3];
    const float* color_emb = (const float*)d_in[4];
    const float* W_node    = (const float*)d_in[5];
    const float* b_node    = (const float*)d_in[6];
    const float* W1_rel    = (const float*)d_in[7];
    const float* W1_root   = (const float*)d_in[8];
    const float* b1        = (const float*)d_in[9];
    const float* W2_rel    = (const float*)d_in[10];
    const float* W2_root   = (const float*)d_in[11];
    const float* b2        = (const float*)d_in[12];
    const float* W_cls     = (const float*)d_in[13];
    const float* b_cls     = (const float*)d_in[14];
    float* out = (float*)d_out;

    const int* src = edge_index;            // edge_index[0, :]
    const int* dst = edge_index + N_EDGES;  // edge_index[1, :]

    const int smem1  = 64 * 72 * 4 + 64 * 64 * 4 + 128 * 68 * 4;   // ~70 KB
    const int smem64 = 128 * 72 * 4 + 64 * 4 + 2 * 128 * 68 * 4;   // ~105 KB
    cudaFuncSetAttribute(conv1_kernel,
                         cudaFuncAttributeMaxDynamicSharedMemorySize, smem1);
    cudaFuncSetAttribute(conv2_kernel,
                         cudaFuncAttributeMaxDynamicSharedMemorySize, smem64);

    prologue_kernel<<<EB + NB + 1, 256>>>(dst, batch, x, shape_emb, color_emb,
                                          W_node, b_node, W1_rel, W1_root, b1);
    scan_kernel<<<N_SCAN_BLKS, SCAN_BLK>>>();
    fill_kernel<<<(N_EDGES + 255) / 256, 256>>>(src, dst);

    conv1_kernel<<<444, 256, smem1>>>();          // 3 blocks/SM resident
    gather64_kernel<<<(N_NODES + 7) / 8, 256>>>();
    conv2_kernel<<<296, 256, smem64>>>(W2_rel, W2_root, b2);  // 2 blocks/SM

    poolcls_kernel<<<N_GRAPHS, 64>>>(W_cls, b_cls, out);
}